// round 16
// baseline (speedup 1.0000x reference)
#include <cuda_runtime.h>
#include <cuda_fp16.h>
#include <cstdint>

#define T_MAX 4096
#define E_MAX 8
#define F_MAXC 2048
#define D_MAXC 1024

typedef unsigned int u32;

// ---------------- device scratch ---------------------------------------------------
__device__ int   g_counts[E_MAX];
__device__ float g_Psum[E_MAX];
__device__ int   g_asg[E_MAX * T_MAX];
__device__ float g_gates[T_MAX * 2];
__device__ __half g_axk [(size_t)E_MAX * (D_MAXC/16) * (T_MAX/64) * 1024];      // gathered x
__device__ __half g_actk[(size_t)E_MAX * (F_MAXC/16) * (T_MAX/64) * 1024];      // silu(g)*v
__device__ __half g_win [(size_t)E_MAX * (D_MAXC/16) * (2*F_MAXC/64) * 1024];   // interleaved (g,v)
__device__ __half g_wout[(size_t)E_MAX * (F_MAXC/16) * (D_MAXC/64) * 1024];
__device__ __half g_yh [(size_t)2 * T_MAX * D_MAXC];                             // gate-scaled y (fp16)

// ---------------- helpers ----------------------------------------------------------
__device__ __forceinline__ u32 s2u(const void* p){
  u32 a; asm("{ .reg .u64 t; cvta.to.shared.u64 t, %1; cvt.u32.u64 %0, t; }" : "=r"(a) : "l"(p));
  return a;
}
__device__ __forceinline__ u32 swz(u32 x){ return x ^ ((x >> 3) & 0x70u); }
__device__ __forceinline__ u32 pack2f16(float a, float b){
  __half ha = __float2half_rn(a), hb = __float2half_rn(b);
  return (u32)__half_as_ushort(ha) | ((u32)__half_as_ushort(hb) << 16);
}
#define MB_INIT(addr, cnt) \
  asm volatile("mbarrier.init.shared.b64 [%0], %1;" :: "r"(addr), "r"((u32)(cnt)) : "memory")
#define MB_WAIT(addr, parity) do { \
  u32 _a=(addr), _p=(u32)(parity), _d; \
  asm volatile("{\n\t.reg .pred P;\n\tmbarrier.try_wait.parity.acquire.cta.shared::cta.b64 P, [%1], %2;\n\tselp.b32 %0,1,0,P;\n\t}" \
    : "=r"(_d) : "r"(_a), "r"(_p) : "memory"); \
  while(!_d){ \
    asm volatile("{\n\t.reg .pred P;\n\tmbarrier.try_wait.parity.acquire.cta.shared::cta.b64 P, [%1], %2, 0x989680;\n\tselp.b32 %0,1,0,P;\n\t}" \
      : "=r"(_d) : "r"(_a), "r"(_p) : "memory"); \
  } \
} while(0)

#define LDMX4T(r, addr) \
  asm volatile("ldmatrix.sync.aligned.m8n8.x4.trans.shared.b16 {%0,%1,%2,%3}, [%4];" \
    : "=r"((r)[0]), "=r"((r)[1]), "=r"((r)[2]), "=r"((r)[3]) : "r"(addr))
#define MMA_F16(c, a, b0, b1) \
  asm volatile("mma.sync.aligned.m16n8k16.row.col.f32.f16.f16.f32 " \
    "{%0,%1,%2,%3}, {%4,%5,%6,%7}, {%8,%9}, {%0,%1,%2,%3};" \
    : "+f"((c)[0]), "+f"((c)[1]), "+f"((c)[2]), "+f"((c)[3]) \
    : "r"((a)[0]), "r"((a)[1]), "r"((a)[2]), "r"((a)[3]), "r"(b0), "r"(b1))

// ---------------- init -------------------------------------------------------------
__global__ void init_k(){
  int i = threadIdx.x;
  if (i < E_MAX){ g_counts[i] = 0; g_Psum[i] = 0.f; }
}

// ---------------- router: smem-cached rw, 16 tokens/block (proven) -----------------
__global__ __launch_bounds__(512)
void router_k(const float* __restrict__ x, const float* __restrict__ rw,
              int T, int E, int D, const int* __restrict__ topk_p){
  __shared__ float srw[E_MAX][D_MAXC];
  __shared__ float sm_p[16][E_MAX];
  int tid = threadIdx.x;
  for (int i = tid; i < D * E; i += 512){
    int d = i / E, e = i - d * E;
    srw[e][d] = rw[i];
  }
  int warp = tid >> 5, lane = tid & 31;
  if (lane == 0){
    #pragma unroll
    for (int e = 0; e < E_MAX; e++) sm_p[warp][e] = 0.f;
  }
  __syncthreads();

  int t = blockIdx.x * 16 + warp;
  if (t < T){
    float acc[E_MAX];
    #pragma unroll
    for (int e = 0; e < E_MAX; e++) acc[e] = 0.f;
    const float* xr = x + (size_t)t * D;
    int iters = D >> 7;
    for (int it = 0; it < iters; it++){
      int d = it * 128 + lane * 4;
      float4 xv = *(const float4*)(xr + d);
      #pragma unroll
      for (int e = 0; e < E_MAX; e++){
        if (e < E){
          float4 r = *(const float4*)&srw[e][d];
          acc[e] += xv.x * r.x;
          acc[e] += xv.y * r.y;
          acc[e] += xv.z * r.z;
          acc[e] += xv.w * r.w;
        }
      }
    }
    #pragma unroll
    for (int e = 0; e < E_MAX; e++){
      #pragma unroll
      for (int off = 16; off; off >>= 1) acc[e] += __shfl_xor_sync(0xffffffffu, acc[e], off);
    }
    if (lane == 0){
      int tk = topk_p ? *topk_p : 2;
      if (tk < 1) tk = 1; if (tk > 2) tk = 2;
      int i0 = 0; float v0 = acc[0];
      for (int e = 1; e < E; e++) if (acc[e] > v0){ v0 = acc[e]; i0 = e; }
      if (tk == 1){
        g_gates[t*2+0] = 1.f; g_gates[t*2+1] = 0.f;
        int p = atomicAdd(&g_counts[i0], 1);
        g_asg[i0*T_MAX + p] = t*2;
      } else {
        int i1 = -1; float v1 = -3.4e38f;
        for (int e = 0; e < E; e++) if (e != i0 && acc[e] > v1){ v1 = acc[e]; i1 = e; }
        float g1 = 1.f / (1.f + __expf(v0 - v1));
        float g0 = 1.f - g1;
        g_gates[t*2+0] = g0; g_gates[t*2+1] = g1;
        int p0 = atomicAdd(&g_counts[i0], 1); g_asg[i0*T_MAX + p0] = t*2;
        int p1 = atomicAdd(&g_counts[i1], 1); g_asg[i1*T_MAX + p1] = t*2 + 1;
      }
      float m = acc[0];
      for (int e = 1; e < E; e++) m = fmaxf(m, acc[e]);
      float s = 0.f; float pe[E_MAX];
      for (int e = 0; e < E; e++){ pe[e] = __expf(acc[e] - m); s += pe[e]; }
      float inv = 1.f / s;
      for (int e = 0; e < E; e++) sm_p[warp][e] = pe[e] * inv;
    }
  }
  __syncthreads();
  if (tid < E){
    float s = 0.f;
    #pragma unroll
    for (int w = 0; w < 16; w++) s += sm_p[w][tid];
    atomicAdd(&g_Psum[tid], s);
  }
}

__global__ void aux_k(float* dst, int T, int E, const int* __restrict__ topk_p){
  if (threadIdx.x == 0 && blockIdx.x == 0){
    int tk = topk_p ? *topk_p : 2;
    if (tk < 1) tk = 1; if (tk > 2) tk = 2;
    float s = 0.f;
    for (int e = 0; e < E; e++){
      float f = (float)g_counts[e] / (float)(T * tk);
      float P = g_Psum[e] / (float)T;
      s += f * P;
    }
    *dst = (float)E * s;
  }
}

// ---------------- gather x -> tiled-swizzled K-major g_axk (proven) ----------------
__global__ void gather_x_k(const float* __restrict__ x, int D){
  int e = blockIdx.z;
  int count = g_counts[e];
  int m0 = blockIdx.y * 64;
  if (m0 >= count) return;
  int d0 = blockIdx.x * 64;
  __shared__ float sm[64][65];
  int tid = threadIdx.x;

  int tk = tid >> 2, dg = (tid & 3) * 16;
  int slot = m0 + tk;
  int token = g_asg[e * T_MAX + (slot < count ? slot : 0)] >> 1;
  const float* xr = x + (size_t)token * D + d0 + dg;
  #pragma unroll
  for (int i = 0; i < 4; i++){
    float4 v = *(const float4*)(xr + i * 4);
    sm[tk][dg + i*4 + 0] = v.x; sm[tk][dg + i*4 + 1] = v.y;
    sm[tk][dg + i*4 + 2] = v.z; sm[tk][dg + i*4 + 3] = v.w;
  }
  __syncthreads();
  int kcl = tid >> 6, kr = (tid >> 2) & 15, mpb = (tid & 3) * 8;
  int KC = D / 16, SA = T_MAX / 64;
  size_t atom = ((size_t)(e * KC + (d0 >> 4) + kcl)) * SA + (m0 >> 6);
  u32* dst = (u32*)g_axk + atom * 512;
  int dloc = kcl * 16 + kr;
  #pragma unroll
  for (int q = 0; q < 2; q++){
    uint4 v;
    int mp = mpb + q * 4;
    v.x = pack2f16(sm[2*mp+0][dloc], sm[2*mp+1][dloc]);
    v.y = pack2f16(sm[2*mp+2][dloc], sm[2*mp+3][dloc]);
    v.z = pack2f16(sm[2*mp+4][dloc], sm[2*mp+5][dloc]);
    v.w = pack2f16(sm[2*mp+6][dloc], sm[2*mp+7][dloc]);
    *(uint4*)(dst + (swz((u32)(kr * 128 + mp * 4)) >> 2)) = v;
  }
}

// ---------------- weight conversions (proven) --------------------------------------
__global__ void conv_win_k(const float* __restrict__ w, int D, int F, size_t nq){
  size_t i = (size_t)blockIdx.x * blockDim.x + threadIdx.x;
  if (i >= nq) return;                             // nq = E*D*F/4
  int qF = F >> 2;
  size_t row = i / qF; int j = (int)(i % qF) * 4;
  int d = (int)(row % D); int e = (int)(row / D);
  const float* src = w + row * (size_t)(2 * F);
  float4 gv = *(const float4*)(src + j);
  float4 vv = *(const float4*)(src + F + j);
  uint4 o;
  o.x = pack2f16(gv.x, vv.x); o.y = pack2f16(gv.y, vv.y);
  o.z = pack2f16(gv.z, vv.z); o.w = pack2f16(gv.w, vv.w);
  int KC = D / 16, NA = (2 * F) / 64;
  size_t atom = ((size_t)(e * KC + (d >> 4))) * NA + (j >> 5);
  *(uint4*)((u32*)g_win + atom * 512 + (swz((u32)((d & 15) * 128 + (j & 31) * 4)) >> 2)) = o;
}

__global__ void conv_wout_k(const float* __restrict__ w, int F, int D, size_t nq){
  size_t i = (size_t)blockIdx.x * blockDim.x + threadIdx.x;
  if (i >= nq) return;                             // nq = E*F*D/8
  int qD = D >> 3;
  size_t row = i / qD; int np = (int)(i % qD) * 4;
  int f = (int)(row % F); int e = (int)(row / F);
  const float* src = w + row * (size_t)D + np * 2;
  float4 s0 = *(const float4*)(src);
  float4 s1 = *(const float4*)(src + 4);
  uint4 o;
  o.x = pack2f16(s0.x, s0.y); o.y = pack2f16(s0.z, s0.w);
  o.z = pack2f16(s1.x, s1.y); o.w = pack2f16(s1.z, s1.w);
  int KC = F / 16, NA = D / 64;
  size_t atom = ((size_t)(e * KC + (f >> 4))) * NA + (np >> 5);
  *(uint4*)((u32*)g_wout + atom * 512 + (swz((u32)((f & 15) * 128 + (np & 31) * 4)) >> 2)) = o;
}

// ---------------- fp16 MMA grouped GEMM: 128 thr, M=128 x N=128, 2 CTAs/SM ---------
// (unchanged from R14 WIN)
template<bool GLU>
__global__ __launch_bounds__(128, 2)
void moe_gemm_mma(const __half* __restrict__ Abase, const __half* __restrict__ Bbase,
                  int KC, int NA, int F, int D){
  int e = blockIdx.z;
  int count = g_counts[e];
  int m0 = blockIdx.y * 128;
  if (m0 >= count) return;
  int n0 = blockIdx.x * 128;

  extern __shared__ char smem[];
  u32 sb = s2u(smem);
  const u32 STG = 32768u, DATA = 128u, BOFF = 16384u;
  int tid = threadIdx.x;
  const int SA = T_MAX / 64;
  int NC = KC >> 2;

  if (tid == 0){
    #pragma unroll
    for (int s = 0; s < 3; s++) MB_INIT(sb + 8u*s, 1);
  }
  __syncthreads();

  auto arm = [&](int c){
    int slot = c % 3;
    u32 st = sb + DATA + (u32)slot * STG;
    u32 bar = sb + 8u * (u32)slot;
    asm volatile("mbarrier.arrive.expect_tx.shared.b64 _, [%0], %1;" :: "r"(bar), "r"(32768u) : "memory");
    #pragma unroll
    for (int s = 0; s < 4; s++){
      const __half* as = Abase + (((size_t)(e * KC + 4*c + s)) * SA + (m0 >> 6)) * 1024;
      asm volatile("cp.async.bulk.shared::cluster.global.mbarrier::complete_tx::bytes [%0], [%1], %2, [%3];"
        :: "r"(st + (u32)s * 4096u), "l"(as), "r"(4096u), "r"(bar) : "memory");
      const __half* bs = Bbase + (((size_t)(e * KC + 4*c + s)) * NA + (n0 >> 6)) * 1024;
      asm volatile("cp.async.bulk.shared::cluster.global.mbarrier::complete_tx::bytes [%0], [%1], %2, [%3];"
        :: "r"(st + BOFF + (u32)s * 4096u), "l"(bs), "r"(4096u), "r"(bar) : "memory");
    }
  };

  if (tid == 0){
    #pragma unroll
    for (int p = 0; p < 3; p++) if (p < NC) arm(p);
  }

  int w = tid >> 5, lane = tid & 31;
  int wm = w >> 1, wn = w & 1;
  u32 preA[4];
  {
    u32 kr = (u32)((lane & 7) + ((lane >> 4) << 3));
    u32 mbase = (u32)(((lane >> 3) & 1) * 8);
    #pragma unroll
    for (int mt = 0; mt < 4; mt++){
      u32 m_in = mbase + (u32)mt * 16u;
      preA[mt] = (u32)wm * 2048u + swz(kr * 128u + m_in * 2u);
    }
  }
  u32 preB[4];
  {
    u32 kr = (u32)((lane & 7) + ((lane >> 3) & 1) * 8);
    #pragma unroll
    for (int bt = 0; bt < 4; bt++){
      u32 nn = (u32)(wn * 64 + (lane >> 4) * 8 + bt * 16);
      preB[bt] = BOFF + (nn >> 6) * 2048u + swz(kr * 128u + (nn & 63u) * 2u);
    }
  }

  float acc[4][8][4];
  #pragma unroll
  for (int i = 0; i < 4; i++)
    #pragma unroll
    for (int j = 0; j < 8; j++)
      #pragma unroll
      for (int q = 0; q < 4; q++) acc[i][j][q] = 0.f;

  for (int c = 0; c < NC; c++){
    int slot = c % 3;
    MB_WAIT(sb + 8u * (u32)slot, (c / 3) & 1);
    __syncwarp();
    u32 base = sb + DATA + (u32)slot * STG;
    #pragma unroll
    for (int ks = 0; ks < 4; ks++){
      u32 rb[16];
      #pragma unroll
      for (int bt = 0; bt < 4; bt++)
        LDMX4T(&rb[bt*4], base + (u32)ks * 4096u + preB[bt]);
      #pragma unroll
      for (int mt = 0; mt < 4; mt++){
        u32 ah[4];
        LDMX4T(ah, base + (u32)ks * 4096u + preA[mt]);
        #pragma unroll
        for (int nt = 0; nt < 8; nt++) MMA_F16(acc[mt][nt], ah, rb[nt*2], rb[nt*2+1]);
      }
    }
    __syncthreads();
    if (tid == 0 && c + 3 < NC){
      asm volatile("fence.proxy.async.shared::cta;" ::: "memory");
      arm(c + 3);
    }
  }

  // ---- epilogue
  int g = lane >> 2, t = lane & 3;
  if (GLU){
    #pragma unroll
    for (int mt = 0; mt < 4; mt++){
      #pragma unroll
      for (int hrow = 0; hrow < 2; hrow++){
        int m_local = wm * 64 + mt * 16 + g + hrow * 8;
        #pragma unroll
        for (int nt = 0; nt < 8; nt++){
          int j_local = wn * 32 + nt * 4 + t;
          float gg = acc[mt][nt][hrow * 2];
          float vv = acc[mt][nt][hrow * 2 + 1];
          float o = (gg / (1.f + __expf(-gg))) * vv;
          u32 off = (u32)(((j_local >> 4) * 2 + (m_local >> 6)) * 2048) +
                    swz((u32)((j_local & 15) * 128 + (m_local & 63) * 2));
          *(__half*)(smem + DATA + off) = __float2half_rn(o);
        }
      }
    }
    __syncthreads();
    if (tid == 0){
      asm volatile("fence.proxy.async.shared::cta;" ::: "memory");
      int jn0 = n0 >> 1;
      int KC2 = F / 16;
      #pragma unroll
      for (int kcl = 0; kcl < 4; kcl++){
        const __half* dst = g_actk + (((size_t)(e * KC2 + (jn0 >> 4) + kcl)) * SA + (m0 >> 6)) * 1024;
        u32 src = sb + DATA + (u32)kcl * 4096u;
        asm volatile("cp.async.bulk.global.shared::cta.bulk_group [%0], [%1], %2;"
          :: "l"(dst), "r"(src), "r"(4096u) : "memory");
      }
      asm volatile("cp.async.bulk.commit_group;" ::: "memory");
      asm volatile("cp.async.bulk.wait_group 0;" ::: "memory");
    }
  } else {
    #pragma unroll
    for (int mt = 0; mt < 4; mt++){
      int rbase = wm * 64 + mt * 16 + g;
      #pragma unroll
      for (int hrow = 0; hrow < 2; hrow++){
        int mg = m0 + rbase + hrow * 8;
        if (mg >= count) continue;
        int a = g_asg[e * T_MAX + mg];
        float gt = g_gates[a];
        #pragma unroll
        for (int nt = 0; nt < 8; nt++){
          int nc = n0 + wn * 64 + nt * 8 + 2 * t;
          __half2 hv = __floats2half2_rn(gt * acc[mt][nt][hrow * 2],
                                         gt * acc[mt][nt][hrow * 2 + 1]);
          *(__half2*)(g_yh + (size_t)a * D + nc) = hv;
        }
      }
    }
  }
}

// ---------------- combine: out = bias + y0 + y1 (gate pre-applied, fp16) -----------
__global__ void combine_k(const float* __restrict__ bias, float* __restrict__ out,
                          int T, int D, const int* __restrict__ topk_p){
  int t = blockIdx.x;
  int tk = topk_p ? *topk_p : 2;
  if (tk < 1) tk = 1; if (tk > 2) tk = 2;
  for (int c = threadIdx.x * 4; c < D; c += 256 * 4){
    float4 o = *(const float4*)(bias + c);
    #pragma unroll
    for (int k = 0; k < 2; k++){
      if (k < tk){
        const __half2* yr = (const __half2*)(g_yh + (size_t)(t*2 + k) * D + c);
        float2 a0 = __half22float2(yr[0]);
        float2 a1 = __half22float2(yr[1]);
        o.x += a0.x; o.y += a0.y; o.z += a1.x; o.w += a1.y;
      }
    }
    *(float4*)(out + (size_t)t * D + c) = o;
  }
}

// ---------------- launch: conv_win overlapped with router+gather only --------------
// GEMMs remain strictly serial after all preprocessing (protects g_win L2 residency).
extern "C" void kernel_launch(void* const* d_in, const int* in_sizes, int n_in,
                              void* d_out, int out_size){
  const float* x     = (const float*)d_in[0];
  const float* rw    = (const float*)d_in[1];
  const float* w_in  = (const float*)d_in[2];
  const float* w_out = (const float*)d_in[3];
  const float* bias  = (const float*)d_in[4];
  const int*   topk  = (n_in >= 6) ? (const int*)d_in[5] : nullptr;

  int D = in_sizes[4];
  int T = in_sizes[0] / D;
  int E = in_sizes[1] / D;
  int F = in_sizes[2] / (2 * D * E);
  float* out = (float*)d_out;

  const int SMEM = 128 + 3 * 32768;      // 98432 -> 2 CTAs/SM
  static cudaStream_t s1 = nullptr;
  static cudaEvent_t evF = nullptr, evW = nullptr;
  if (!s1){
    cudaStreamCreateWithFlags(&s1, cudaStreamNonBlocking);
    cudaEventCreateWithFlags(&evF, cudaEventDisableTiming);
    cudaEventCreateWithFlags(&evW, cudaEventDisableTiming);
    cudaFuncSetAttribute(moe_gemm_mma<true>,  cudaFuncAttributeMaxDynamicSharedMemorySize, SMEM);
    cudaFuncSetAttribute(moe_gemm_mma<false>, cudaFuncAttributeMaxDynamicSharedMemorySize, SMEM);
  }

  // fork: conv_win on side stream (no L2-residency stakes vs router/gather)
  cudaEventRecord(evF, 0);
  cudaStreamWaitEvent(s1, evF, 0);
  size_t nwin = (size_t)E * D * F / 4;
  conv_win_k<<<(unsigned)((nwin + 255) / 256), 256, 0, s1>>>(w_in, D, F, nwin);
  cudaEventRecord(evW, s1);

  // main chain: routing + gather
  init_k<<<1, 32>>>();
  router_k<<<(T + 15) / 16, 512>>>(x, rw, T, E, D, topk);
  if (out_size > T * D) aux_k<<<1, 1>>>(out + (size_t)T * D, T, E, topk);
  {
    dim3 gg(D / 64, T_MAX / 64, E);
    gather_x_k<<<gg, 256>>>(x, D);
  }

  // join BEFORE anything GEMM-related; conv_wout stays serial too
  cudaStreamWaitEvent(0, evW, 0);
  size_t nwo = (size_t)E * F * D / 8;
  conv_wout_k<<<(unsigned)((nwo + 255) / 256), 256>>>(w_out, F, D, nwo);

  const __half *axk, *actk, *win, *wout;
  cudaGetSymbolAddress((void**)&axk,  g_axk);
  cudaGetSymbolAddress((void**)&actk, g_actk);
  cudaGetSymbolAddress((void**)&win,  g_win);
  cudaGetSymbolAddress((void**)&wout, g_wout);

  int mblocks = T_MAX / 128;
  dim3 g1((2 * F) / 128, mblocks, E);
  moe_gemm_mma<true><<<g1, 128, SMEM>>>(axk, win, D / 16, (2 * F) / 64, F, D);

  dim3 g2(D / 128, mblocks, E);
  moe_gemm_mma<false><<<g2, 128, SMEM>>>(actk, wout, F / 16, D / 64, F, D);

  combine_k<<<T, 256>>>(bias, out, T, D, topk);
}

// round 17
// speedup vs baseline: 1.0260x; 1.0260x over previous
#include <cuda_runtime.h>
#include <cuda_fp16.h>
#include <cstdint>

#define T_MAX 4096
#define E_MAX 8
#define F_MAXC 2048
#define D_MAXC 1024

typedef unsigned int u32;

// ---------------- device scratch ---------------------------------------------------
// NOTE: g_counts / g_Psum start zero (module-load zero-init) and are re-zeroed at the
// END of every call by combine_k, so no init kernel is needed.
__device__ int   g_counts[E_MAX];
__device__ float g_Psum[E_MAX];
__device__ int   g_asg[E_MAX * T_MAX];
__device__ float g_gates[T_MAX * 2];
__device__ __half g_axk [(size_t)E_MAX * (D_MAXC/16) * (T_MAX/64) * 1024];      // gathered x
__device__ __half g_actk[(size_t)E_MAX * (F_MAXC/16) * (T_MAX/64) * 1024];      // silu(g)*v
__device__ __half g_win [(size_t)E_MAX * (D_MAXC/16) * (2*F_MAXC/64) * 1024];   // interleaved (g,v)
__device__ __half g_wout[(size_t)E_MAX * (F_MAXC/16) * (D_MAXC/64) * 1024];
__device__ __half g_yh [(size_t)2 * T_MAX * D_MAXC];                             // gate-scaled y (fp16)

// ---------------- helpers ----------------------------------------------------------
__device__ __forceinline__ u32 s2u(const void* p){
  u32 a; asm("{ .reg .u64 t; cvta.to.shared.u64 t, %1; cvt.u32.u64 %0, t; }" : "=r"(a) : "l"(p));
  return a;
}
__device__ __forceinline__ u32 swz(u32 x){ return x ^ ((x >> 3) & 0x70u); }
__device__ __forceinline__ u32 pack2f16(float a, float b){
  __half ha = __float2half_rn(a), hb = __float2half_rn(b);
  return (u32)__half_as_ushort(ha) | ((u32)__half_as_ushort(hb) << 16);
}
#define MB_INIT(addr, cnt) \
  asm volatile("mbarrier.init.shared.b64 [%0], %1;" :: "r"(addr), "r"((u32)(cnt)) : "memory")
#define MB_WAIT(addr, parity) do { \
  u32 _a=(addr), _p=(u32)(parity), _d; \
  asm volatile("{\n\t.reg .pred P;\n\tmbarrier.try_wait.parity.acquire.cta.shared::cta.b64 P, [%1], %2;\n\tselp.b32 %0,1,0,P;\n\t}" \
    : "=r"(_d) : "r"(_a), "r"(_p) : "memory"); \
  while(!_d){ \
    asm volatile("{\n\t.reg .pred P;\n\tmbarrier.try_wait.parity.acquire.cta.shared::cta.b64 P, [%1], %2, 0x989680;\n\tselp.b32 %0,1,0,P;\n\t}" \
      : "=r"(_d) : "r"(_a), "r"(_p) : "memory"); \
  } \
} while(0)

#define LDMX4T(r, addr) \
  asm volatile("ldmatrix.sync.aligned.m8n8.x4.trans.shared.b16 {%0,%1,%2,%3}, [%4];" \
    : "=r"((r)[0]), "=r"((r)[1]), "=r"((r)[2]), "=r"((r)[3]) : "r"(addr))
#define MMA_F16(c, a, b0, b1) \
  asm volatile("mma.sync.aligned.m16n8k16.row.col.f32.f16.f16.f32 " \
    "{%0,%1,%2,%3}, {%4,%5,%6,%7}, {%8,%9}, {%0,%1,%2,%3};" \
    : "+f"((c)[0]), "+f"((c)[1]), "+f"((c)[2]), "+f"((c)[3]) \
    : "r"((a)[0]), "r"((a)[1]), "r"((a)[2]), "r"((a)[3]), "r"(b0), "r"(b1))

// ---------------- router: smem-cached rw, 16 tokens/block (proven) -----------------
__global__ __launch_bounds__(512)
void router_k(const float* __restrict__ x, const float* __restrict__ rw,
              int T, int E, int D, const int* __restrict__ topk_p){
  __shared__ float srw[E_MAX][D_MAXC];
  __shared__ float sm_p[16][E_MAX];
  int tid = threadIdx.x;
  for (int i = tid; i < D * E; i += 512){
    int d = i / E, e = i - d * E;
    srw[e][d] = rw[i];
  }
  int warp = tid >> 5, lane = tid & 31;
  if (lane == 0){
    #pragma unroll
    for (int e = 0; e < E_MAX; e++) sm_p[warp][e] = 0.f;
  }
  __syncthreads();

  int t = blockIdx.x * 16 + warp;
  if (t < T){
    float acc[E_MAX];
    #pragma unroll
    for (int e = 0; e < E_MAX; e++) acc[e] = 0.f;
    const float* xr = x + (size_t)t * D;
    int iters = D >> 7;
    for (int it = 0; it < iters; it++){
      int d = it * 128 + lane * 4;
      float4 xv = *(const float4*)(xr + d);
      #pragma unroll
      for (int e = 0; e < E_MAX; e++){
        if (e < E){
          float4 r = *(const float4*)&srw[e][d];
          acc[e] += xv.x * r.x;
          acc[e] += xv.y * r.y;
          acc[e] += xv.z * r.z;
          acc[e] += xv.w * r.w;
        }
      }
    }
    #pragma unroll
    for (int e = 0; e < E_MAX; e++){
      #pragma unroll
      for (int off = 16; off; off >>= 1) acc[e] += __shfl_xor_sync(0xffffffffu, acc[e], off);
    }
    if (lane == 0){
      int tk = topk_p ? *topk_p : 2;
      if (tk < 1) tk = 1; if (tk > 2) tk = 2;
      int i0 = 0; float v0 = acc[0];
      for (int e = 1; e < E; e++) if (acc[e] > v0){ v0 = acc[e]; i0 = e; }
      if (tk == 1){
        g_gates[t*2+0] = 1.f; g_gates[t*2+1] = 0.f;
        int p = atomicAdd(&g_counts[i0], 1);
        g_asg[i0*T_MAX + p] = t*2;
      } else {
        int i1 = -1; float v1 = -3.4e38f;
        for (int e = 0; e < E; e++) if (e != i0 && acc[e] > v1){ v1 = acc[e]; i1 = e; }
        float g1 = 1.f / (1.f + __expf(v0 - v1));
        float g0 = 1.f - g1;
        g_gates[t*2+0] = g0; g_gates[t*2+1] = g1;
        int p0 = atomicAdd(&g_counts[i0], 1); g_asg[i0*T_MAX + p0] = t*2;
        int p1 = atomicAdd(&g_counts[i1], 1); g_asg[i1*T_MAX + p1] = t*2 + 1;
      }
      float m = acc[0];
      for (int e = 1; e < E; e++) m = fmaxf(m, acc[e]);
      float s = 0.f; float pe[E_MAX];
      for (int e = 0; e < E; e++){ pe[e] = __expf(acc[e] - m); s += pe[e]; }
      float inv = 1.f / s;
      for (int e = 0; e < E; e++) sm_p[warp][e] = pe[e] * inv;
    }
  }
  __syncthreads();
  if (tid < E){
    float s = 0.f;
    #pragma unroll
    for (int w = 0; w < 16; w++) s += sm_p[w][tid];
    atomicAdd(&g_Psum[tid], s);
  }
}

// ---------------- gather x -> tiled-swizzled K-major g_axk (proven) ----------------
__global__ void gather_x_k(const float* __restrict__ x, int D){
  int e = blockIdx.z;
  int count = g_counts[e];
  int m0 = blockIdx.y * 64;
  if (m0 >= count) return;
  int d0 = blockIdx.x * 64;
  __shared__ float sm[64][65];
  int tid = threadIdx.x;

  int tk = tid >> 2, dg = (tid & 3) * 16;
  int slot = m0 + tk;
  int token = g_asg[e * T_MAX + (slot < count ? slot : 0)] >> 1;
  const float* xr = x + (size_t)token * D + d0 + dg;
  #pragma unroll
  for (int i = 0; i < 4; i++){
    float4 v = *(const float4*)(xr + i * 4);
    sm[tk][dg + i*4 + 0] = v.x; sm[tk][dg + i*4 + 1] = v.y;
    sm[tk][dg + i*4 + 2] = v.z; sm[tk][dg + i*4 + 3] = v.w;
  }
  __syncthreads();
  int kcl = tid >> 6, kr = (tid >> 2) & 15, mpb = (tid & 3) * 8;
  int KC = D / 16, SA = T_MAX / 64;
  size_t atom = ((size_t)(e * KC + (d0 >> 4) + kcl)) * SA + (m0 >> 6);
  u32* dst = (u32*)g_axk + atom * 512;
  int dloc = kcl * 16 + kr;
  #pragma unroll
  for (int q = 0; q < 2; q++){
    uint4 v;
    int mp = mpb + q * 4;
    v.x = pack2f16(sm[2*mp+0][dloc], sm[2*mp+1][dloc]);
    v.y = pack2f16(sm[2*mp+2][dloc], sm[2*mp+3][dloc]);
    v.z = pack2f16(sm[2*mp+4][dloc], sm[2*mp+5][dloc]);
    v.w = pack2f16(sm[2*mp+6][dloc], sm[2*mp+7][dloc]);
    *(uint4*)(dst + (swz((u32)(kr * 128 + mp * 4)) >> 2)) = v;
  }
}

// ---------------- weight conversions (proven) --------------------------------------
__global__ void conv_win_k(const float* __restrict__ w, int D, int F, size_t nq){
  size_t i = (size_t)blockIdx.x * blockDim.x + threadIdx.x;
  if (i >= nq) return;                             // nq = E*D*F/4
  int qF = F >> 2;
  size_t row = i / qF; int j = (int)(i % qF) * 4;
  int d = (int)(row % D); int e = (int)(row / D);
  const float* src = w + row * (size_t)(2 * F);
  float4 gv = *(const float4*)(src + j);
  float4 vv = *(const float4*)(src + F + j);
  uint4 o;
  o.x = pack2f16(gv.x, vv.x); o.y = pack2f16(gv.y, vv.y);
  o.z = pack2f16(gv.z, vv.z); o.w = pack2f16(gv.w, vv.w);
  int KC = D / 16, NA = (2 * F) / 64;
  size_t atom = ((size_t)(e * KC + (d >> 4))) * NA + (j >> 5);
  *(uint4*)((u32*)g_win + atom * 512 + (swz((u32)((d & 15) * 128 + (j & 31) * 4)) >> 2)) = o;
}

__global__ void conv_wout_k(const float* __restrict__ w, int F, int D, size_t nq){
  size_t i = (size_t)blockIdx.x * blockDim.x + threadIdx.x;
  if (i >= nq) return;                             // nq = E*F*D/8
  int qD = D >> 3;
  size_t row = i / qD; int np = (int)(i % qD) * 4;
  int f = (int)(row % F); int e = (int)(row / F);
  const float* src = w + row * (size_t)D + np * 2;
  float4 s0 = *(const float4*)(src);
  float4 s1 = *(const float4*)(src + 4);
  uint4 o;
  o.x = pack2f16(s0.x, s0.y); o.y = pack2f16(s0.z, s0.w);
  o.z = pack2f16(s1.x, s1.y); o.w = pack2f16(s1.z, s1.w);
  int KC = F / 16, NA = D / 64;
  size_t atom = ((size_t)(e * KC + (f >> 4))) * NA + (np >> 5);
  *(uint4*)((u32*)g_wout + atom * 512 + (swz((u32)((f & 15) * 128 + (np & 31) * 4)) >> 2)) = o;
}

// ---------------- fp16 MMA grouped GEMM: 128 thr, M=128 x N=128, 2 CTAs/SM ---------
// (unchanged from R14 WIN)
template<bool GLU>
__global__ __launch_bounds__(128, 2)
void moe_gemm_mma(const __half* __restrict__ Abase, const __half* __restrict__ Bbase,
                  int KC, int NA, int F, int D){
  int e = blockIdx.z;
  int count = g_counts[e];
  int m0 = blockIdx.y * 128;
  if (m0 >= count) return;
  int n0 = blockIdx.x * 128;

  extern __shared__ char smem[];
  u32 sb = s2u(smem);
  const u32 STG = 32768u, DATA = 128u, BOFF = 16384u;
  int tid = threadIdx.x;
  const int SA = T_MAX / 64;
  int NC = KC >> 2;

  if (tid == 0){
    #pragma unroll
    for (int s = 0; s < 3; s++) MB_INIT(sb + 8u*s, 1);
  }
  __syncthreads();

  auto arm = [&](int c){
    int slot = c % 3;
    u32 st = sb + DATA + (u32)slot * STG;
    u32 bar = sb + 8u * (u32)slot;
    asm volatile("mbarrier.arrive.expect_tx.shared.b64 _, [%0], %1;" :: "r"(bar), "r"(32768u) : "memory");
    #pragma unroll
    for (int s = 0; s < 4; s++){
      const __half* as = Abase + (((size_t)(e * KC + 4*c + s)) * SA + (m0 >> 6)) * 1024;
      asm volatile("cp.async.bulk.shared::cluster.global.mbarrier::complete_tx::bytes [%0], [%1], %2, [%3];"
        :: "r"(st + (u32)s * 4096u), "l"(as), "r"(4096u), "r"(bar) : "memory");
      const __half* bs = Bbase + (((size_t)(e * KC + 4*c + s)) * NA + (n0 >> 6)) * 1024;
      asm volatile("cp.async.bulk.shared::cluster.global.mbarrier::complete_tx::bytes [%0], [%1], %2, [%3];"
        :: "r"(st + BOFF + (u32)s * 4096u), "l"(bs), "r"(4096u), "r"(bar) : "memory");
    }
  };

  if (tid == 0){
    #pragma unroll
    for (int p = 0; p < 3; p++) if (p < NC) arm(p);
  }

  int w = tid >> 5, lane = tid & 31;
  int wm = w >> 1, wn = w & 1;
  u32 preA[4];
  {
    u32 kr = (u32)((lane & 7) + ((lane >> 4) << 3));
    u32 mbase = (u32)(((lane >> 3) & 1) * 8);
    #pragma unroll
    for (int mt = 0; mt < 4; mt++){
      u32 m_in = mbase + (u32)mt * 16u;
      preA[mt] = (u32)wm * 2048u + swz(kr * 128u + m_in * 2u);
    }
  }
  u32 preB[4];
  {
    u32 kr = (u32)((lane & 7) + ((lane >> 3) & 1) * 8);
    #pragma unroll
    for (int bt = 0; bt < 4; bt++){
      u32 nn = (u32)(wn * 64 + (lane >> 4) * 8 + bt * 16);
      preB[bt] = BOFF + (nn >> 6) * 2048u + swz(kr * 128u + (nn & 63u) * 2u);
    }
  }

  float acc[4][8][4];
  #pragma unroll
  for (int i = 0; i < 4; i++)
    #pragma unroll
    for (int j = 0; j < 8; j++)
      #pragma unroll
      for (int q = 0; q < 4; q++) acc[i][j][q] = 0.f;

  for (int c = 0; c < NC; c++){
    int slot = c % 3;
    MB_WAIT(sb + 8u * (u32)slot, (c / 3) & 1);
    __syncwarp();
    u32 base = sb + DATA + (u32)slot * STG;
    #pragma unroll
    for (int ks = 0; ks < 4; ks++){
      u32 rb[16];
      #pragma unroll
      for (int bt = 0; bt < 4; bt++)
        LDMX4T(&rb[bt*4], base + (u32)ks * 4096u + preB[bt]);
      #pragma unroll
      for (int mt = 0; mt < 4; mt++){
        u32 ah[4];
        LDMX4T(ah, base + (u32)ks * 4096u + preA[mt]);
        #pragma unroll
        for (int nt = 0; nt < 8; nt++) MMA_F16(acc[mt][nt], ah, rb[nt*2], rb[nt*2+1]);
      }
    }
    __syncthreads();
    if (tid == 0 && c + 3 < NC){
      asm volatile("fence.proxy.async.shared::cta;" ::: "memory");
      arm(c + 3);
    }
  }

  // ---- epilogue
  int g = lane >> 2, t = lane & 3;
  if (GLU){
    #pragma unroll
    for (int mt = 0; mt < 4; mt++){
      #pragma unroll
      for (int hrow = 0; hrow < 2; hrow++){
        int m_local = wm * 64 + mt * 16 + g + hrow * 8;
        #pragma unroll
        for (int nt = 0; nt < 8; nt++){
          int j_local = wn * 32 + nt * 4 + t;
          float gg = acc[mt][nt][hrow * 2];
          float vv = acc[mt][nt][hrow * 2 + 1];
          float o = (gg / (1.f + __expf(-gg))) * vv;
          u32 off = (u32)(((j_local >> 4) * 2 + (m_local >> 6)) * 2048) +
                    swz((u32)((j_local & 15) * 128 + (m_local & 63) * 2));
          *(__half*)(smem + DATA + off) = __float2half_rn(o);
        }
      }
    }
    __syncthreads();
    if (tid == 0){
      asm volatile("fence.proxy.async.shared::cta;" ::: "memory");
      int jn0 = n0 >> 1;
      int KC2 = F / 16;
      #pragma unroll
      for (int kcl = 0; kcl < 4; kcl++){
        const __half* dst = g_actk + (((size_t)(e * KC2 + (jn0 >> 4) + kcl)) * SA + (m0 >> 6)) * 1024;
        u32 src = sb + DATA + (u32)kcl * 4096u;
        asm volatile("cp.async.bulk.global.shared::cta.bulk_group [%0], [%1], %2;"
          :: "l"(dst), "r"(src), "r"(4096u) : "memory");
      }
      asm volatile("cp.async.bulk.commit_group;" ::: "memory");
      asm volatile("cp.async.bulk.wait_group 0;" ::: "memory");
    }
  } else {
    #pragma unroll
    for (int mt = 0; mt < 4; mt++){
      int rbase = wm * 64 + mt * 16 + g;
      #pragma unroll
      for (int hrow = 0; hrow < 2; hrow++){
        int mg = m0 + rbase + hrow * 8;
        if (mg >= count) continue;
        int a = g_asg[e * T_MAX + mg];
        float gt = g_gates[a];
        #pragma unroll
        for (int nt = 0; nt < 8; nt++){
          int nc = n0 + wn * 64 + nt * 8 + 2 * t;
          __half2 hv = __floats2half2_rn(gt * acc[mt][nt][hrow * 2],
                                         gt * acc[mt][nt][hrow * 2 + 1]);
          *(__half2*)(g_yh + (size_t)a * D + nc) = hv;
        }
      }
    }
  }
}

// ---------------- combine: out = bias + y0 + y1; block 0 also computes aux ---------
// and re-zeroes g_counts/g_Psum for the next invocation (replaces init_k + aux_k).
__global__ void combine_k(const float* __restrict__ bias, float* __restrict__ out,
                          int T, int E, int D, const int* __restrict__ topk_p,
                          int do_aux){
  int t = blockIdx.x;
  int tk = topk_p ? *topk_p : 2;
  if (tk < 1) tk = 1; if (tk > 2) tk = 2;
  for (int c = threadIdx.x * 4; c < D; c += 256 * 4){
    float4 o = *(const float4*)(bias + c);
    #pragma unroll
    for (int k = 0; k < 2; k++){
      if (k < tk){
        const __half2* yr = (const __half2*)(g_yh + (size_t)(t*2 + k) * D + c);
        float2 a0 = __half22float2(yr[0]);
        float2 a1 = __half22float2(yr[1]);
        o.x += a0.x; o.y += a0.y; o.z += a1.x; o.w += a1.y;
      }
    }
    *(float4*)(out + (size_t)t * D + c) = o;
  }
  if (blockIdx.x == 0 && threadIdx.x == 0){
    if (do_aux){
      float s = 0.f;
      for (int e = 0; e < E; e++){
        float f = (float)g_counts[e] / (float)(T * tk);
        float P = g_Psum[e] / (float)T;
        s += f * P;
      }
      out[(size_t)T * D] = (float)E * s;
    }
    // reset for next invocation (initial state is module-load zero-init)
    for (int e = 0; e < E_MAX; e++){ g_counts[e] = 0; g_Psum[e] = 0.f; }
  }
}

// ---------------- launch (serial, proven schedule; init/aux folded) ----------------
extern "C" void kernel_launch(void* const* d_in, const int* in_sizes, int n_in,
                              void* d_out, int out_size){
  const float* x     = (const float*)d_in[0];
  const float* rw    = (const float*)d_in[1];
  const float* w_in  = (const float*)d_in[2];
  const float* w_out = (const float*)d_in[3];
  const float* bias  = (const float*)d_in[4];
  const int*   topk  = (n_in >= 6) ? (const int*)d_in[5] : nullptr;

  int D = in_sizes[4];
  int T = in_sizes[0] / D;
  int E = in_sizes[1] / D;
  int F = in_sizes[2] / (2 * D * E);
  float* out = (float*)d_out;

  const int SMEM = 128 + 3 * 32768;      // 98432 -> 2 CTAs/SM
  cudaFuncSetAttribute(moe_gemm_mma<true>,  cudaFuncAttributeMaxDynamicSharedMemorySize, SMEM);
  cudaFuncSetAttribute(moe_gemm_mma<false>, cudaFuncAttributeMaxDynamicSharedMemorySize, SMEM);

  router_k<<<(T + 15) / 16, 512>>>(x, rw, T, E, D, topk);

  {
    dim3 gg(D / 64, T_MAX / 64, E);
    gather_x_k<<<gg, 256>>>(x, D);
  }
  size_t nwin = (size_t)E * D * F / 4;
  conv_win_k<<<(unsigned)((nwin + 255) / 256), 256>>>(w_in, D, F, nwin);
  size_t nwo = (size_t)E * F * D / 8;
  conv_wout_k<<<(unsigned)((nwo + 255) / 256), 256>>>(w_out, F, D, nwo);

  const __half *axk, *actk, *win, *wout;
  cudaGetSymbolAddress((void**)&axk,  g_axk);
  cudaGetSymbolAddress((void**)&actk, g_actk);
  cudaGetSymbolAddress((void**)&win,  g_win);
  cudaGetSymbolAddress((void**)&wout, g_wout);

  int mblocks = T_MAX / 128;
  dim3 g1((2 * F) / 128, mblocks, E);
  moe_gemm_mma<true><<<g1, 128, SMEM>>>(axk, win, D / 16, (2 * F) / 64, F, D);

  dim3 g2(D / 128, mblocks, E);
  moe_gemm_mma<false><<<g2, 128, SMEM>>>(actk, wout, F / 16, D / 64, F, D);

  int do_aux = (out_size > T * D) ? 1 : 0;
  combine_k<<<T, 256>>>(bias, out, T, E, D, topk, do_aux);
}